// round 9
// baseline (speedup 1.0000x reference)
#include <cuda_runtime.h>
#include <cuda_bf16.h>
#include <cstdint>

// ---------------------------------------------------------------------------
// SphericalLinear on GB300 (PTX target sm_103 plain: no tcgen05 available).
// R9: GEMM = R8 compute structure, but SMEM rows 64B + XOR chunk swizzle
//     (stage 40KB -> 32KB), 3-stage cp.async ring (fully unrolled, static
//     stage idx), ONE __syncthreads per chunk, refill issued right after the
//     barrier. 2 CTAs/SM preserved (2 x 97KB < 227KB). Front-end as R8.
// ---------------------------------------------------------------------------

#define NFILT   4
#define C_IN    256
#define C_OUT   512
#define TILE_M  128
#define TILE_N  128
#define KC      32
#define NCHUNKS (C_IN / KC)          // 8
#define NSTAGE  3
#define MAXP    65536
#define CAP     32768                 // fixed bucket capacity (rows)
#define CAPT    (CAP / TILE_M)        // 256 tiles per filter
#define PADROWS (NFILT * CAP)         // 131072
#define THREADS 256

// SMEM: bf16 rows of 32 elems = 64B, XOR chunk swizzle c^=((r>>1)&3)
// -> conflict-free ldmatrix AND dense (no padding).
#define MAT_SZ  (TILE_M * 64)         // 8192 B per matrix
#define OFF_AH  0
#define OFF_AL  (MAT_SZ)
#define OFF_BH  (2 * MAT_SZ)
#define OFF_BL  (3 * MAT_SZ)
#define STAGE_SZ (4 * MAT_SZ)         // 32768
#define SM_PERM  0
#define SM_TILE  1024
#define SMEM_TOTAL (SM_TILE + NSTAGE * STAGE_SZ)   // 99328 B

// ---- device scratch --------------------------------------------------------
__device__ int d_perm[PADROWS];
__device__ int d_fill[NFILT];
__device__ __nv_bfloat16 d_Ahi[(size_t)PADROWS * C_IN];
__device__ __nv_bfloat16 d_Alo[(size_t)PADROWS * C_IN];
__device__ __nv_bfloat16 d_Whi[(size_t)NFILT * C_OUT * C_IN];
__device__ __nv_bfloat16 d_Wlo[(size_t)NFILT * C_OUT * C_IN];

// ---- helpers ---------------------------------------------------------------
__device__ __forceinline__ uint32_t smem_u32(const void* p) {
    uint32_t a;
    asm("{ .reg .u64 t; cvta.to.shared.u64 t, %1; cvt.u32.u64 %0, t; }" : "=r"(a) : "l"(p));
    return a;
}
__device__ __forceinline__ void cp16(uint32_t dst, const void* src) {
    asm volatile("cp.async.cg.shared.global [%0], [%1], 16;" :: "r"(dst), "l"(src) : "memory");
}
#define CP_COMMIT() asm volatile("cp.async.commit_group;" ::: "memory")
#define CP_WAIT1()  asm volatile("cp.async.wait_group 1;" ::: "memory")

__device__ __forceinline__ void ldsm4(uint32_t* r, uint32_t addr) {
    asm volatile("ldmatrix.sync.aligned.m8n8.x4.shared.b16 {%0,%1,%2,%3}, [%4];"
                 : "=r"(r[0]), "=r"(r[1]), "=r"(r[2]), "=r"(r[3]) : "r"(addr));
}
__device__ __forceinline__ void mma_bf16(float* c, const uint32_t* a,
                                         uint32_t b0, uint32_t b1) {
    asm volatile("mma.sync.aligned.m16n8k16.row.col.f32.bf16.bf16.f32 "
                 "{%0,%1,%2,%3}, {%4,%5,%6,%7}, {%8,%9}, {%0,%1,%2,%3};"
                 : "+f"(c[0]), "+f"(c[1]), "+f"(c[2]), "+f"(c[3])
                 : "r"(a[0]), "r"(a[1]), "r"(a[2]), "r"(a[3]), "r"(b0), "r"(b1));
}

// fp32 -> (bf16 hi, bf16 lo) packed pairs
__device__ __forceinline__ void cvt_split2(float a0, float a1, uint32_t& hi, uint32_t& lo) {
    uint32_t p;
    asm("cvt.rn.bf16x2.f32 %0, %1, %2;" : "=r"(p) : "f"(a1), "f"(a0));
    float h0 = __uint_as_float(p << 16);
    float h1 = __uint_as_float(p & 0xFFFF0000u);
    float r0 = a0 - h0;
    float r1 = a1 - h1;
    uint32_t q;
    asm("cvt.rn.bf16x2.f32 %0, %1, %2;" : "=r"(q) : "f"(r1), "f"(r0));
    hi = p; lo = q;
}
__device__ __forceinline__ void cvt_split8(float4 v0, float4 v1, uint4& hi, uint4& lo) {
    cvt_split2(v0.x, v0.y, hi.x, lo.x);
    cvt_split2(v0.z, v0.w, hi.y, lo.y);
    cvt_split2(v1.x, v1.y, hi.z, lo.z);
    cvt_split2(v1.z, v1.w, hi.w, lo.w);
}

// ---- front-end kernels -----------------------------------------------------
__global__ void reset_kernel() {
    int t = threadIdx.x;
    if (t < NFILT) d_fill[t] = 0;
}

__global__ void classify_scatter_kernel(const float* __restrict__ xyz, int P) {
    __shared__ int sc[NFILT];
    __shared__ int sbase[NFILT];
    int tid = threadIdx.x;
    if (tid < NFILT) sc[tid] = 0;
    __syncthreads();
    int p = blockIdx.x * blockDim.x + tid;
    int f = 0, rank = 0;
    if (p < P) {
        float x = xyz[3 * p + 0], y = xyz[3 * p + 1], z = xyz[3 * p + 2];
        float r = sqrtf(x * x + y * y + z * z);
        if      (r < 1.0f)   f = 0;
        else if (r < 1.5f)   f = 1;
        else if (r < 2.0f)   f = 2;
        else if (r < 100.0f) f = 3;
        else                 f = 0;   // argmax of all-False -> 0 (matches jnp)
        rank = atomicAdd(&sc[f], 1);
    }
    __syncthreads();
    if (tid < NFILT) sbase[tid] = (sc[tid] != 0) ? atomicAdd(&d_fill[tid], sc[tid]) : 0;
    __syncthreads();
    if (p < P) d_perm[f * CAP + sbase[f] + rank] = p;
}

__global__ void pack_all_kernel(const float* __restrict__ feat,
                                const float* __restrict__ weight,
                                int featBlocks) {
    int tid = threadIdx.x;
    int col = (tid & 31) * 8;
    if ((int)blockIdx.x < featBlocks) {
        int q = blockIdx.x * 8 + (tid >> 5);       // padded global row
        int f = q >> 15;                           // q / CAP
        int local = q & (CAP - 1);
        int cnt = d_fill[f];
        int rcnt = (cnt + TILE_M - 1) & ~(TILE_M - 1);
        if (local >= rcnt) return;                 // beyond used+padded region
        uint4 hi = {0, 0, 0, 0}, lo = {0, 0, 0, 0};
        if (local < cnt) {
            int p = d_perm[q];
            const float4* src = (const float4*)(feat + (size_t)p * C_IN + col);
            cvt_split8(src[0], src[1], hi, lo);
        }
        *(uint4*)(d_Ahi + (size_t)q * C_IN + col) = hi;
        *(uint4*)(d_Alo + (size_t)q * C_IN + col) = lo;
    } else {
        int q = (blockIdx.x - featBlocks) * 8 + (tid >> 5);   // weight row
        if (q >= NFILT * C_OUT) return;
        const float4* src = (const float4*)(weight + (size_t)q * C_IN + col);
        uint4 hi, lo;
        cvt_split8(src[0], src[1], hi, lo);
        *(uint4*)(d_Whi + (size_t)q * C_IN + col) = hi;
        *(uint4*)(d_Wlo + (size_t)q * C_IN + col) = lo;
    }
}

// ---- GEMM ------------------------------------------------------------------
__global__ void __launch_bounds__(THREADS)
gemm_mma_kernel(const float* __restrict__ bias, float* __restrict__ out) {
    extern __shared__ char smem[];
    const int tid = threadIdx.x;
    const int lane = tid & 31;
    const int wid = tid >> 5;
    const int wm = wid >> 2;          // 0..1
    const int wn = wid & 3;           // 0..3
    const int by = blockIdx.y;

    const int f = blockIdx.x >> 8;                 // blockIdx.x / CAPT
    const int rowbase = blockIdx.x * TILE_M;       // padded global row base
    int nval = d_fill[f] - (int)((blockIdx.x & (CAPT - 1)) * TILE_M);
    if (nval <= 0) return;
    if (nval > TILE_M) nval = TILE_M;

    int* sPerm = (int*)(smem + SM_PERM);
    if (tid < TILE_M) {
        sPerm[tid] = (tid < nval) ? d_perm[rowbase + tid] : d_perm[rowbase];
    }

    const uint32_t sb = smem_u32(smem) + SM_TILE;

    const char* srcA_h = (const char*)(d_Ahi + (size_t)rowbase * C_IN);
    const char* srcA_l = (const char*)(d_Alo + (size_t)rowbase * C_IN);
    const size_t wrow = ((size_t)f * C_OUT + (size_t)by * TILE_N) * C_IN;
    const char* srcB_h = (const char*)(d_Whi + wrow);
    const char* srcB_l = (const char*)(d_Wlo + wrow);

    // stage loader: 4 matrices x 128 rows x 4 swizzled 16B chunks
    auto load_stage = [&](int c, int s) {
        const int ktB = c * KC * 2;                 // byte offset into 512B rows
        const uint32_t base = sb + s * STAGE_SZ;
        #pragma unroll
        for (int it = 0; it < 2; it++) {
            int idx = it * THREADS + tid;           // 0..511
            int r = idx >> 2;
            int cc = idx & 3;
            int sw = (cc ^ ((r >> 1) & 3)) * 16;
            uint32_t d0 = base + r * 64 + sw;
            size_t   so = (size_t)r * 512 + ktB + cc * 16;
            cp16(d0 + OFF_AH, srcA_h + so);
            cp16(d0 + OFF_AL, srcA_l + so);
            cp16(d0 + OFF_BH, srcB_h + so);
            cp16(d0 + OFF_BL, srcB_l + so);
        }
        CP_COMMIT();
    };

    load_stage(0, 0);
    load_stage(1, 1);

    // ldmatrix lane address components (swizzle selector is per-lane constant:
    // row steps of 16 do not change (row>>1)&3)
    const int rA = ((lane >> 3) & 1) * 8 + (lane & 7);   // row within m16 tile
    const int kA = (lane >> 4);                          // k chunk sel (0/1)
    const int rB = (lane >> 4) * 8 + (lane & 7);         // row within n16 tile
    const int kB = ((lane >> 3) & 1);
    const int rowA0 = wm * 64 + rA;
    const int rowB0 = wn * 32 + rB;
    const int swzA = (rowA0 >> 1) & 3;
    const int swzB = (rowB0 >> 1) & 3;

    float acc[4][4][4];
    #pragma unroll
    for (int i = 0; i < 4; i++)
        #pragma unroll
        for (int j = 0; j < 4; j++)
            #pragma unroll
            for (int e = 0; e < 4; e++) acc[i][j][e] = 0.0f;

    #pragma unroll
    for (int c = 0; c < NCHUNKS; c++) {
        const int s = c % NSTAGE;                  // static after full unroll
        const uint32_t base = sb + s * STAGE_SZ;
        CP_WAIT1();
        __syncthreads();                           // single barrier per chunk
        // refill the stage chunk c-1 vacated; overlaps with compute below
        if (c + 2 < NCHUNKS) load_stage(c + 2, (c + 2) % NSTAGE);

        #pragma unroll
        for (int k16 = 0; k16 < 2; k16++) {
            const int kseg = k16 * 2;
            const int chA = ((kseg + kA) ^ swzA) * 16;
            const int chB = ((kseg + kB) ^ swzB) * 16;
            uint32_t ah[4][4], al[4][4];
            uint32_t bh[2][4], bl[2][4];
            #pragma unroll
            for (int mi = 0; mi < 4; mi++) {
                uint32_t ad = base + (rowA0 + mi * 16) * 64 + chA;
                ldsm4(ah[mi], ad + OFF_AH);
                ldsm4(al[mi], ad + OFF_AL);
            }
            #pragma unroll
            for (int nj = 0; nj < 2; nj++) {
                uint32_t bd = base + (rowB0 + nj * 16) * 64 + chB;
                ldsm4(bh[nj], bd + OFF_BH);
                ldsm4(bl[nj], bd + OFF_BL);
            }
            #pragma unroll
            for (int mi = 0; mi < 4; mi++) {
                #pragma unroll
                for (int n8 = 0; n8 < 4; n8++) {
                    const int nj = n8 >> 1, h = (n8 & 1) * 2;
                    mma_bf16(acc[mi][n8], ah[mi], bh[nj][h], bh[nj][h + 1]);
                    mma_bf16(acc[mi][n8], ah[mi], bl[nj][h], bl[nj][h + 1]);
                    mma_bf16(acc[mi][n8], al[mi], bh[nj][h], bh[nj][h + 1]);
                }
            }
        }
    }

    // ---- epilogue: bias + scattered stores ----
    const int g = lane >> 2;
    const int a2 = (lane & 3) * 2;
    float2 bv[4];
    #pragma unroll
    for (int ni = 0; ni < 4; ni++)
        bv[ni] = *(const float2*)(bias + (size_t)f * C_OUT + by * TILE_N + wn * 32 + ni * 8 + a2);

    #pragma unroll
    for (int mi = 0; mi < 4; mi++) {
        #pragma unroll
        for (int half = 0; half < 2; half++) {
            int ml = wm * 64 + mi * 16 + g + half * 8;
            if (ml < nval) {
                float* orow = out + (size_t)sPerm[ml] * C_OUT + by * TILE_N + wn * 32;
                #pragma unroll
                for (int ni = 0; ni < 4; ni++) {
                    float2 v;
                    v.x = acc[mi][ni][half * 2 + 0] + bv[ni].x;
                    v.y = acc[mi][ni][half * 2 + 1] + bv[ni].y;
                    *(float2*)(orow + ni * 8 + a2) = v;
                }
            }
        }
    }
}

// ---------------------------------------------------------------------------
extern "C" void kernel_launch(void* const* d_in, const int* in_sizes, int n_in,
                              void* d_out, int out_size) {
    const float* feat   = (const float*)d_in[0];
    const float* xyz    = (const float*)d_in[1];
    const float* weight = (const float*)d_in[2];
    const float* bias   = (const float*)d_in[3];
    float* out = (float*)d_out;

    const int P = in_sizes[0] / C_IN;

    cudaFuncSetAttribute(gemm_mma_kernel,
                         cudaFuncAttributeMaxDynamicSharedMemorySize, SMEM_TOTAL);

    reset_kernel<<<1, 32>>>();
    classify_scatter_kernel<<<(P + 255) / 256, 256>>>(xyz, P);

    const int featBlocks = PADROWS / 8;
    const int wBlocks = (NFILT * C_OUT) / 8;
    pack_all_kernel<<<featBlocks + wBlocks, 256>>>(feat, weight, featBlocks);

    dim3 grid(NFILT * CAPT, C_OUT / TILE_N);
    gemm_mma_kernel<<<grid, THREADS, SMEM_TOTAL>>>(bias, out);
}

// round 10
// speedup vs baseline: 1.7349x; 1.7349x over previous
#include <cuda_runtime.h>
#include <cuda_bf16.h>
#include <cstdint>

// ---------------------------------------------------------------------------
// SphericalLinear on GB300 (PTX target sm_103 plain: no tcgen05 available).
// R10: R9 GEMM structure (64B swizzled rows, 3-stage cp.async ring, ONE
//      __syncthreads per chunk, refill right after barrier) PLUS
//      __launch_bounds__(256,2) to force regs<=128 so 2 CTAs/SM co-reside
//      (R9 compiled to 130 regs -> regfile evicted the 2nd CTA).
// ---------------------------------------------------------------------------

#define NFILT   4
#define C_IN    256
#define C_OUT   512
#define TILE_M  128
#define TILE_N  128
#define KC      32
#define NCHUNKS (C_IN / KC)          // 8
#define NSTAGE  3
#define MAXP    65536
#define CAP     32768                 // fixed bucket capacity (rows)
#define CAPT    (CAP / TILE_M)        // 256 tiles per filter
#define PADROWS (NFILT * CAP)         // 131072
#define THREADS 256

// SMEM: bf16 rows of 32 elems = 64B, XOR chunk swizzle c^=((r>>1)&3)
#define MAT_SZ  (TILE_M * 64)         // 8192 B per matrix
#define OFF_AH  0
#define OFF_AL  (MAT_SZ)
#define OFF_BH  (2 * MAT_SZ)
#define OFF_BL  (3 * MAT_SZ)
#define STAGE_SZ (4 * MAT_SZ)         // 32768
#define SM_PERM  0
#define SM_TILE  1024
#define SMEM_TOTAL (SM_TILE + NSTAGE * STAGE_SZ)   // 99328 B (2/SM fits)

// ---- device scratch --------------------------------------------------------
__device__ int d_perm[PADROWS];
__device__ int d_fill[NFILT];
__device__ __nv_bfloat16 d_Ahi[(size_t)PADROWS * C_IN];
__device__ __nv_bfloat16 d_Alo[(size_t)PADROWS * C_IN];
__device__ __nv_bfloat16 d_Whi[(size_t)NFILT * C_OUT * C_IN];
__device__ __nv_bfloat16 d_Wlo[(size_t)NFILT * C_OUT * C_IN];

// ---- helpers ---------------------------------------------------------------
__device__ __forceinline__ uint32_t smem_u32(const void* p) {
    uint32_t a;
    asm("{ .reg .u64 t; cvta.to.shared.u64 t, %1; cvt.u32.u64 %0, t; }" : "=r"(a) : "l"(p));
    return a;
}
__device__ __forceinline__ void cp16(uint32_t dst, const void* src) {
    asm volatile("cp.async.cg.shared.global [%0], [%1], 16;" :: "r"(dst), "l"(src) : "memory");
}
#define CP_COMMIT() asm volatile("cp.async.commit_group;" ::: "memory")
#define CP_WAIT1()  asm volatile("cp.async.wait_group 1;" ::: "memory")

__device__ __forceinline__ void ldsm4(uint32_t* r, uint32_t addr) {
    asm volatile("ldmatrix.sync.aligned.m8n8.x4.shared.b16 {%0,%1,%2,%3}, [%4];"
                 : "=r"(r[0]), "=r"(r[1]), "=r"(r[2]), "=r"(r[3]) : "r"(addr));
}
__device__ __forceinline__ void mma_bf16(float* c, const uint32_t* a,
                                         uint32_t b0, uint32_t b1) {
    asm volatile("mma.sync.aligned.m16n8k16.row.col.f32.bf16.bf16.f32 "
                 "{%0,%1,%2,%3}, {%4,%5,%6,%7}, {%8,%9}, {%0,%1,%2,%3};"
                 : "+f"(c[0]), "+f"(c[1]), "+f"(c[2]), "+f"(c[3])
                 : "r"(a[0]), "r"(a[1]), "r"(a[2]), "r"(a[3]), "r"(b0), "r"(b1));
}

// fp32 -> (bf16 hi, bf16 lo) packed pairs
__device__ __forceinline__ void cvt_split2(float a0, float a1, uint32_t& hi, uint32_t& lo) {
    uint32_t p;
    asm("cvt.rn.bf16x2.f32 %0, %1, %2;" : "=r"(p) : "f"(a1), "f"(a0));
    float h0 = __uint_as_float(p << 16);
    float h1 = __uint_as_float(p & 0xFFFF0000u);
    float r0 = a0 - h0;
    float r1 = a1 - h1;
    uint32_t q;
    asm("cvt.rn.bf16x2.f32 %0, %1, %2;" : "=r"(q) : "f"(r1), "f"(r0));
    hi = p; lo = q;
}
__device__ __forceinline__ void cvt_split8(float4 v0, float4 v1, uint4& hi, uint4& lo) {
    cvt_split2(v0.x, v0.y, hi.x, lo.x);
    cvt_split2(v0.z, v0.w, hi.y, lo.y);
    cvt_split2(v1.x, v1.y, hi.z, lo.z);
    cvt_split2(v1.z, v1.w, hi.w, lo.w);
}

// ---- front-end kernels -----------------------------------------------------
__global__ void reset_kernel() {
    int t = threadIdx.x;
    if (t < NFILT) d_fill[t] = 0;
}

__global__ void classify_scatter_kernel(const float* __restrict__ xyz, int P) {
    __shared__ int sc[NFILT];
    __shared__ int sbase[NFILT];
    int tid = threadIdx.x;
    if (tid < NFILT) sc[tid] = 0;
    __syncthreads();
    int p = blockIdx.x * blockDim.x + tid;
    int f = 0, rank = 0;
    if (p < P) {
        float x = xyz[3 * p + 0], y = xyz[3 * p + 1], z = xyz[3 * p + 2];
        float r = sqrtf(x * x + y * y + z * z);
        if      (r < 1.0f)   f = 0;
        else if (r < 1.5f)   f = 1;
        else if (r < 2.0f)   f = 2;
        else if (r < 100.0f) f = 3;
        else                 f = 0;   // argmax of all-False -> 0 (matches jnp)
        rank = atomicAdd(&sc[f], 1);
    }
    __syncthreads();
    if (tid < NFILT) sbase[tid] = (sc[tid] != 0) ? atomicAdd(&d_fill[tid], sc[tid]) : 0;
    __syncthreads();
    if (p < P) d_perm[f * CAP + sbase[f] + rank] = p;
}

__global__ void pack_all_kernel(const float* __restrict__ feat,
                                const float* __restrict__ weight,
                                int featBlocks) {
    int tid = threadIdx.x;
    int col = (tid & 31) * 8;
    if ((int)blockIdx.x < featBlocks) {
        int q = blockIdx.x * 8 + (tid >> 5);       // padded global row
        int f = q >> 15;                           // q / CAP
        int local = q & (CAP - 1);
        int cnt = d_fill[f];
        int rcnt = (cnt + TILE_M - 1) & ~(TILE_M - 1);
        if (local >= rcnt) return;                 // beyond used+padded region
        uint4 hi = {0, 0, 0, 0}, lo = {0, 0, 0, 0};
        if (local < cnt) {
            int p = d_perm[q];
            const float4* src = (const float4*)(feat + (size_t)p * C_IN + col);
            cvt_split8(src[0], src[1], hi, lo);
        }
        *(uint4*)(d_Ahi + (size_t)q * C_IN + col) = hi;
        *(uint4*)(d_Alo + (size_t)q * C_IN + col) = lo;
    } else {
        int q = (blockIdx.x - featBlocks) * 8 + (tid >> 5);   // weight row
        if (q >= NFILT * C_OUT) return;
        const float4* src = (const float4*)(weight + (size_t)q * C_IN + col);
        uint4 hi, lo;
        cvt_split8(src[0], src[1], hi, lo);
        *(uint4*)(d_Whi + (size_t)q * C_IN + col) = hi;
        *(uint4*)(d_Wlo + (size_t)q * C_IN + col) = lo;
    }
}

// ---- GEMM ------------------------------------------------------------------
__global__ void __launch_bounds__(THREADS, 2)
gemm_mma_kernel(const float* __restrict__ bias, float* __restrict__ out) {
    extern __shared__ char smem[];
    const int tid = threadIdx.x;
    const int lane = tid & 31;
    const int wid = tid >> 5;
    const int wm = wid >> 2;          // 0..1
    const int wn = wid & 3;           // 0..3
    const int by = blockIdx.y;

    const int f = blockIdx.x >> 8;                 // blockIdx.x / CAPT
    const int rowbase = blockIdx.x * TILE_M;       // padded global row base
    int nval = d_fill[f] - (int)((blockIdx.x & (CAPT - 1)) * TILE_M);
    if (nval <= 0) return;
    if (nval > TILE_M) nval = TILE_M;

    int* sPerm = (int*)(smem + SM_PERM);
    if (tid < TILE_M) {
        sPerm[tid] = (tid < nval) ? d_perm[rowbase + tid] : d_perm[rowbase];
    }

    const uint32_t sb = smem_u32(smem) + SM_TILE;

    const char* srcA_h = (const char*)(d_Ahi + (size_t)rowbase * C_IN);
    const char* srcA_l = (const char*)(d_Alo + (size_t)rowbase * C_IN);
    const size_t wrow = ((size_t)f * C_OUT + (size_t)by * TILE_N) * C_IN;
    const char* srcB_h = (const char*)(d_Whi + wrow);
    const char* srcB_l = (const char*)(d_Wlo + wrow);

    // stage loader: 4 matrices x 128 rows x 4 swizzled 16B chunks
    auto load_stage = [&](int c, int s) {
        const int ktB = c * KC * 2;                 // byte offset into 512B rows
        const uint32_t base = sb + s * STAGE_SZ;
        #pragma unroll
        for (int it = 0; it < 2; it++) {
            int idx = it * THREADS + tid;           // 0..511
            int r = idx >> 2;
            int cc = idx & 3;
            int sw = (cc ^ ((r >> 1) & 3)) * 16;
            uint32_t d0 = base + r * 64 + sw;
            size_t   so = (size_t)r * 512 + ktB + cc * 16;
            cp16(d0 + OFF_AH, srcA_h + so);
            cp16(d0 + OFF_AL, srcA_l + so);
            cp16(d0 + OFF_BH, srcB_h + so);
            cp16(d0 + OFF_BL, srcB_l + so);
        }
        CP_COMMIT();
    };

    load_stage(0, 0);
    load_stage(1, 1);

    // ldmatrix lane address components: swizzle selector per-lane constant
    // (16-row steps don't change (row>>1)&3); chunk offsets precomputed for
    // both k16 phases to keep live-register count minimal.
    const int rA = ((lane >> 3) & 1) * 8 + (lane & 7);
    const int kA = (lane >> 4);
    const int rB = (lane >> 4) * 8 + (lane & 7);
    const int kB = ((lane >> 3) & 1);
    const int rowA0 = wm * 64 + rA;
    const int rowB0 = wn * 32 + rB;
    const uint32_t adA0 = (uint32_t)(rowA0 * 64 + ((kA ^ ((rowA0 >> 1) & 3)) * 16));
    const uint32_t adA1 = (uint32_t)(rowA0 * 64 + (((2 + kA) ^ ((rowA0 >> 1) & 3)) * 16));
    const uint32_t adB0 = (uint32_t)(rowB0 * 64 + ((kB ^ ((rowB0 >> 1) & 3)) * 16));
    const uint32_t adB1 = (uint32_t)(rowB0 * 64 + (((2 + kB) ^ ((rowB0 >> 1) & 3)) * 16));

    float acc[4][4][4];
    #pragma unroll
    for (int i = 0; i < 4; i++)
        #pragma unroll
        for (int j = 0; j < 4; j++)
            #pragma unroll
            for (int e = 0; e < 4; e++) acc[i][j][e] = 0.0f;

    #pragma unroll
    for (int c = 0; c < NCHUNKS; c++) {
        const int s = c % NSTAGE;                  // static after full unroll
        const uint32_t base = sb + s * STAGE_SZ;
        CP_WAIT1();
        __syncthreads();                           // single barrier per chunk
        if (c + 2 < NCHUNKS) load_stage(c + 2, (c + 2) % NSTAGE);

        #pragma unroll
        for (int k16 = 0; k16 < 2; k16++) {
            const uint32_t aoff = base + (k16 ? adA1 : adA0);
            const uint32_t boff = base + (k16 ? adB1 : adB0);
            uint32_t ah[4][4], al[4][4];
            uint32_t bh[2][4], bl[2][4];
            #pragma unroll
            for (int mi = 0; mi < 4; mi++) {
                uint32_t ad = aoff + mi * (16 * 64);
                ldsm4(ah[mi], ad + OFF_AH);
                ldsm4(al[mi], ad + OFF_AL);
            }
            #pragma unroll
            for (int nj = 0; nj < 2; nj++) {
                uint32_t bd = boff + nj * (16 * 64);
                ldsm4(bh[nj], bd + OFF_BH);
                ldsm4(bl[nj], bd + OFF_BL);
            }
            #pragma unroll
            for (int mi = 0; mi < 4; mi++) {
                #pragma unroll
                for (int n8 = 0; n8 < 4; n8++) {
                    const int nj = n8 >> 1, h = (n8 & 1) * 2;
                    mma_bf16(acc[mi][n8], ah[mi], bh[nj][h], bh[nj][h + 1]);
                    mma_bf16(acc[mi][n8], ah[mi], bl[nj][h], bl[nj][h + 1]);
                    mma_bf16(acc[mi][n8], al[mi], bh[nj][h], bh[nj][h + 1]);
                }
            }
        }
    }

    // ---- epilogue: bias + scattered stores ----
    const int g = lane >> 2;
    const int a2 = (lane & 3) * 2;
    float2 bv[4];
    #pragma unroll
    for (int ni = 0; ni < 4; ni++)
        bv[ni] = *(const float2*)(bias + (size_t)f * C_OUT + by * TILE_N + wn * 32 + ni * 8 + a2);

    #pragma unroll
    for (int mi = 0; mi < 4; mi++) {
        #pragma unroll
        for (int half = 0; half < 2; half++) {
            int ml = wm * 64 + mi * 16 + g + half * 8;
            if (ml < nval) {
                float* orow = out + (size_t)sPerm[ml] * C_OUT + by * TILE_N + wn * 32;
                #pragma unroll
                for (int ni = 0; ni < 4; ni++) {
                    float2 v;
                    v.x = acc[mi][ni][half * 2 + 0] + bv[ni].x;
                    v.y = acc[mi][ni][half * 2 + 1] + bv[ni].y;
                    *(float2*)(orow + ni * 8 + a2) = v;
                }
            }
        }
    }
}

// ---------------------------------------------------------------------------
extern "C" void kernel_launch(void* const* d_in, const int* in_sizes, int n_in,
                              void* d_out, int out_size) {
    const float* feat   = (const float*)d_in[0];
    const float* xyz    = (const float*)d_in[1];
    const float* weight = (const float*)d_in[2];
    const float* bias   = (const float*)d_in[3];
    float* out = (float*)d_out;

    const int P = in_sizes[0] / C_IN;

    cudaFuncSetAttribute(gemm_mma_kernel,
                         cudaFuncAttributeMaxDynamicSharedMemorySize, SMEM_TOTAL);

    reset_kernel<<<1, 32>>>();
    classify_scatter_kernel<<<(P + 255) / 256, 256>>>(xyz, P);

    const int featBlocks = PADROWS / 8;
    const int wBlocks = (NFILT * C_OUT) / 8;
    pack_all_kernel<<<featBlocks + wBlocks, 256>>>(feat, weight, featBlocks);

    dim3 grid(NFILT * CAPT, C_OUT / TILE_N);
    gemm_mma_kernel<<<grid, THREADS, SMEM_TOTAL>>>(bias, out);
}

// round 11
// speedup vs baseline: 2.1576x; 1.2437x over previous
#include <cuda_runtime.h>
#include <cuda_fp16.h>
#include <cstdint>

// ---------------------------------------------------------------------------
// SphericalLinear on GB300 (PTX target sm_103 plain: no tcgen05 available).
// R11: fp16 2-term split GEMM:  out ~= (Ah + Al) * Bh,  Ah/Al = fp16 split of
//      feat (exact to 2^-22), Bh = fp16(weight) (dropped Bl term ~2^-11 rel).
//      HMMA count drops 3->2 vs the bf16 3-split. Structure = R10 (3-stage
//      cp.async ring, one __syncthreads/chunk, 64B swizzled rows, 2 CTAs/SM).
// ---------------------------------------------------------------------------

#define NFILT   4
#define C_IN    256
#define C_OUT   512
#define TILE_M  128
#define TILE_N  128
#define KC      32
#define NCHUNKS (C_IN / KC)          // 8
#define NSTAGE  3
#define MAXP    65536
#define CAP     32768                 // fixed bucket capacity (rows)
#define CAPT    (CAP / TILE_M)        // 256 tiles per filter
#define PADROWS (NFILT * CAP)         // 131072
#define THREADS 256

// SMEM: fp16 rows of 32 elems = 64B, XOR chunk swizzle c^=((r>>1)&3)
#define MAT_SZ  (TILE_M * 64)         // 8192 B per matrix
#define OFF_AH  0
#define OFF_AL  (MAT_SZ)
#define OFF_BH  (2 * MAT_SZ)
#define STAGE_SZ (3 * MAT_SZ)         // 24576
#define SM_PERM  0
#define SM_TILE  1024
#define SMEM_TOTAL (SM_TILE + NSTAGE * STAGE_SZ)   // 74752 B (2/SM fits)

// ---- device scratch --------------------------------------------------------
__device__ int d_perm[PADROWS];
__device__ int d_fill[NFILT];
__device__ __half d_Ahi[(size_t)PADROWS * C_IN];
__device__ __half d_Alo[(size_t)PADROWS * C_IN];
__device__ __half d_Whi[(size_t)NFILT * C_OUT * C_IN];

// ---- helpers ---------------------------------------------------------------
__device__ __forceinline__ uint32_t smem_u32(const void* p) {
    uint32_t a;
    asm("{ .reg .u64 t; cvta.to.shared.u64 t, %1; cvt.u32.u64 %0, t; }" : "=r"(a) : "l"(p));
    return a;
}
__device__ __forceinline__ void cp16(uint32_t dst, const void* src) {
    asm volatile("cp.async.cg.shared.global [%0], [%1], 16;" :: "r"(dst), "l"(src) : "memory");
}
#define CP_COMMIT() asm volatile("cp.async.commit_group;" ::: "memory")
#define CP_WAIT1()  asm volatile("cp.async.wait_group 1;" ::: "memory")

__device__ __forceinline__ void ldsm4(uint32_t* r, uint32_t addr) {
    asm volatile("ldmatrix.sync.aligned.m8n8.x4.shared.b16 {%0,%1,%2,%3}, [%4];"
                 : "=r"(r[0]), "=r"(r[1]), "=r"(r[2]), "=r"(r[3]) : "r"(addr));
}
__device__ __forceinline__ void mma_f16(float* c, const uint32_t* a,
                                        uint32_t b0, uint32_t b1) {
    asm volatile("mma.sync.aligned.m16n8k16.row.col.f32.f16.f16.f32 "
                 "{%0,%1,%2,%3}, {%4,%5,%6,%7}, {%8,%9}, {%0,%1,%2,%3};"
                 : "+f"(c[0]), "+f"(c[1]), "+f"(c[2]), "+f"(c[3])
                 : "r"(a[0]), "r"(a[1]), "r"(a[2]), "r"(a[3]), "r"(b0), "r"(b1));
}

// fp32 -> (fp16 hi, fp16 lo) packed pairs
__device__ __forceinline__ void cvt_split2_h(float a0, float a1, uint32_t& hi, uint32_t& lo) {
    __half2 h = __floats2half2_rn(a0, a1);
    float2 hf = __half22float2(h);
    __half2 l = __floats2half2_rn(a0 - hf.x, a1 - hf.y);
    hi = *reinterpret_cast<uint32_t*>(&h);
    lo = *reinterpret_cast<uint32_t*>(&l);
}
__device__ __forceinline__ void cvt_split8_h(float4 v0, float4 v1, uint4& hi, uint4& lo) {
    cvt_split2_h(v0.x, v0.y, hi.x, lo.x);
    cvt_split2_h(v0.z, v0.w, hi.y, lo.y);
    cvt_split2_h(v1.x, v1.y, hi.z, lo.z);
    cvt_split2_h(v1.z, v1.w, hi.w, lo.w);
}
__device__ __forceinline__ uint4 cvt8_h(float4 v0, float4 v1) {
    uint4 hi;
    __half2 h0 = __floats2half2_rn(v0.x, v0.y);
    __half2 h1 = __floats2half2_rn(v0.z, v0.w);
    __half2 h2 = __floats2half2_rn(v1.x, v1.y);
    __half2 h3 = __floats2half2_rn(v1.z, v1.w);
    hi.x = *reinterpret_cast<uint32_t*>(&h0);
    hi.y = *reinterpret_cast<uint32_t*>(&h1);
    hi.z = *reinterpret_cast<uint32_t*>(&h2);
    hi.w = *reinterpret_cast<uint32_t*>(&h3);
    return hi;
}

// ---- front-end kernels -----------------------------------------------------
__global__ void reset_kernel() {
    int t = threadIdx.x;
    if (t < NFILT) d_fill[t] = 0;
}

__global__ void classify_scatter_kernel(const float* __restrict__ xyz, int P) {
    __shared__ int sc[NFILT];
    __shared__ int sbase[NFILT];
    int tid = threadIdx.x;
    if (tid < NFILT) sc[tid] = 0;
    __syncthreads();
    int p = blockIdx.x * blockDim.x + tid;
    int f = 0, rank = 0;
    if (p < P) {
        float x = xyz[3 * p + 0], y = xyz[3 * p + 1], z = xyz[3 * p + 2];
        float r = sqrtf(x * x + y * y + z * z);
        if      (r < 1.0f)   f = 0;
        else if (r < 1.5f)   f = 1;
        else if (r < 2.0f)   f = 2;
        else if (r < 100.0f) f = 3;
        else                 f = 0;   // argmax of all-False -> 0 (matches jnp)
        rank = atomicAdd(&sc[f], 1);
    }
    __syncthreads();
    if (tid < NFILT) sbase[tid] = (sc[tid] != 0) ? atomicAdd(&d_fill[tid], sc[tid]) : 0;
    __syncthreads();
    if (p < P) d_perm[f * CAP + sbase[f] + rank] = p;
}

__global__ void pack_all_kernel(const float* __restrict__ feat,
                                const float* __restrict__ weight,
                                int featBlocks) {
    int tid = threadIdx.x;
    int col = (tid & 31) * 8;
    if ((int)blockIdx.x < featBlocks) {
        int q = blockIdx.x * 8 + (tid >> 5);       // padded global row
        int f = q >> 15;                           // q / CAP
        int local = q & (CAP - 1);
        int cnt = d_fill[f];
        int rcnt = (cnt + TILE_M - 1) & ~(TILE_M - 1);
        if (local >= rcnt) return;                 // beyond used+padded region
        uint4 hi = {0, 0, 0, 0}, lo = {0, 0, 0, 0};
        if (local < cnt) {
            int p = d_perm[q];
            const float4* src = (const float4*)(feat + (size_t)p * C_IN + col);
            cvt_split8_h(src[0], src[1], hi, lo);
        }
        *(uint4*)(d_Ahi + (size_t)q * C_IN + col) = hi;
        *(uint4*)(d_Alo + (size_t)q * C_IN + col) = lo;
    } else {
        int q = (blockIdx.x - featBlocks) * 8 + (tid >> 5);   // weight row
        if (q >= NFILT * C_OUT) return;
        const float4* src = (const float4*)(weight + (size_t)q * C_IN + col);
        *(uint4*)(d_Whi + (size_t)q * C_IN + col) = cvt8_h(src[0], src[1]);
    }
}

// ---- GEMM ------------------------------------------------------------------
__global__ void __launch_bounds__(THREADS, 2)
gemm_mma_kernel(const float* __restrict__ bias, float* __restrict__ out) {
    extern __shared__ char smem[];
    const int tid = threadIdx.x;
    const int lane = tid & 31;
    const int wid = tid >> 5;
    const int wm = wid >> 2;          // 0..1
    const int wn = wid & 3;           // 0..3
    const int by = blockIdx.y;

    const int f = blockIdx.x >> 8;                 // blockIdx.x / CAPT
    const int rowbase = blockIdx.x * TILE_M;       // padded global row base
    int nval = d_fill[f] - (int)((blockIdx.x & (CAPT - 1)) * TILE_M);
    if (nval <= 0) return;
    if (nval > TILE_M) nval = TILE_M;

    int* sPerm = (int*)(smem + SM_PERM);
    if (tid < TILE_M) {
        sPerm[tid] = (tid < nval) ? d_perm[rowbase + tid] : d_perm[rowbase];
    }

    const uint32_t sb = smem_u32(smem) + SM_TILE;

    const char* srcA_h = (const char*)(d_Ahi + (size_t)rowbase * C_IN);
    const char* srcA_l = (const char*)(d_Alo + (size_t)rowbase * C_IN);
    const size_t wrow = ((size_t)f * C_OUT + (size_t)by * TILE_N) * C_IN;
    const char* srcB_h = (const char*)(d_Whi + wrow);

    // stage loader: 3 matrices x 128 rows x 4 swizzled 16B chunks
    auto load_stage = [&](int c, int s) {
        const int ktB = c * KC * 2;                 // byte offset into 512B rows
        const uint32_t base = sb + s * STAGE_SZ;
        #pragma unroll
        for (int it = 0; it < 2; it++) {
            int idx = it * THREADS + tid;           // 0..511
            int r = idx >> 2;
            int cc = idx & 3;
            int sw = (cc ^ ((r >> 1) & 3)) * 16;
            uint32_t d0 = base + r * 64 + sw;
            size_t   so = (size_t)r * 512 + ktB + cc * 16;
            cp16(d0 + OFF_AH, srcA_h + so);
            cp16(d0 + OFF_AL, srcA_l + so);
            cp16(d0 + OFF_BH, srcB_h + so);
        }
        CP_COMMIT();
    };

    load_stage(0, 0);
    load_stage(1, 1);

    // ldmatrix lane address components: swizzle selector per-lane constant;
    // chunk offsets precomputed for both k16 phases.
    const int rA = ((lane >> 3) & 1) * 8 + (lane & 7);
    const int kA = (lane >> 4);
    const int rB = (lane >> 4) * 8 + (lane & 7);
    const int kB = ((lane >> 3) & 1);
    const int rowA0 = wm * 64 + rA;
    const int rowB0 = wn * 32 + rB;
    const uint32_t adA0 = (uint32_t)(rowA0 * 64 + ((kA ^ ((rowA0 >> 1) & 3)) * 16));
    const uint32_t adA1 = (uint32_t)(rowA0 * 64 + (((2 + kA) ^ ((rowA0 >> 1) & 3)) * 16));
    const uint32_t adB0 = (uint32_t)(rowB0 * 64 + ((kB ^ ((rowB0 >> 1) & 3)) * 16));
    const uint32_t adB1 = (uint32_t)(rowB0 * 64 + (((2 + kB) ^ ((rowB0 >> 1) & 3)) * 16));

    float acc[4][4][4];
    #pragma unroll
    for (int i = 0; i < 4; i++)
        #pragma unroll
        for (int j = 0; j < 4; j++)
            #pragma unroll
            for (int e = 0; e < 4; e++) acc[i][j][e] = 0.0f;

    #pragma unroll
    for (int c = 0; c < NCHUNKS; c++) {
        const int s = c % NSTAGE;                  // static after full unroll
        const uint32_t base = sb + s * STAGE_SZ;
        CP_WAIT1();
        __syncthreads();                           // single barrier per chunk
        if (c + 2 < NCHUNKS) load_stage(c + 2, (c + 2) % NSTAGE);

        #pragma unroll
        for (int k16 = 0; k16 < 2; k16++) {
            const uint32_t aoff = base + (k16 ? adA1 : adA0);
            const uint32_t boff = base + (k16 ? adB1 : adB0);
            uint32_t ah[4][4], al[4][4];
            uint32_t bh[2][4];
            #pragma unroll
            for (int mi = 0; mi < 4; mi++) {
                uint32_t ad = aoff + mi * (16 * 64);
                ldsm4(ah[mi], ad + OFF_AH);
                ldsm4(al[mi], ad + OFF_AL);
            }
            #pragma unroll
            for (int nj = 0; nj < 2; nj++) {
                ldsm4(bh[nj], boff + nj * (16 * 64) + OFF_BH);
            }
            #pragma unroll
            for (int mi = 0; mi < 4; mi++) {
                #pragma unroll
                for (int n8 = 0; n8 < 4; n8++) {
                    const int nj = n8 >> 1, h = (n8 & 1) * 2;
                    mma_f16(acc[mi][n8], ah[mi], bh[nj][h], bh[nj][h + 1]);
                    mma_f16(acc[mi][n8], al[mi], bh[nj][h], bh[nj][h + 1]);
                }
            }
        }
    }

    // ---- epilogue: bias + scattered stores ----
    const int g = lane >> 2;
    const int a2 = (lane & 3) * 2;
    float2 bv[4];
    #pragma unroll
    for (int ni = 0; ni < 4; ni++)
        bv[ni] = *(const float2*)(bias + (size_t)f * C_OUT + by * TILE_N + wn * 32 + ni * 8 + a2);

    #pragma unroll
    for (int mi = 0; mi < 4; mi++) {
        #pragma unroll
        for (int half = 0; half < 2; half++) {
            int ml = wm * 64 + mi * 16 + g + half * 8;
            if (ml < nval) {
                float* orow = out + (size_t)sPerm[ml] * C_OUT + by * TILE_N + wn * 32;
                #pragma unroll
                for (int ni = 0; ni < 4; ni++) {
                    float2 v;
                    v.x = acc[mi][ni][half * 2 + 0] + bv[ni].x;
                    v.y = acc[mi][ni][half * 2 + 1] + bv[ni].y;
                    *(float2*)(orow + ni * 8 + a2) = v;
                }
            }
        }
    }
}

// ---------------------------------------------------------------------------
extern "C" void kernel_launch(void* const* d_in, const int* in_sizes, int n_in,
                              void* d_out, int out_size) {
    const float* feat   = (const float*)d_in[0];
    const float* xyz    = (const float*)d_in[1];
    const float* weight = (const float*)d_in[2];
    const float* bias   = (const float*)d_in[3];
    float* out = (float*)d_out;

    const int P = in_sizes[0] / C_IN;

    cudaFuncSetAttribute(gemm_mma_kernel,
                         cudaFuncAttributeMaxDynamicSharedMemorySize, SMEM_TOTAL);

    reset_kernel<<<1, 32>>>();
    classify_scatter_kernel<<<(P + 255) / 256, 256>>>(xyz, P);

    const int featBlocks = PADROWS / 8;
    const int wBlocks = (NFILT * C_OUT) / 8;
    pack_all_kernel<<<featBlocks + wBlocks, 256>>>(feat, weight, featBlocks);

    dim3 grid(NFILT * CAPT, C_OUT / TILE_N);
    gemm_mma_kernel<<<grid, THREADS, SMEM_TOTAL>>>(bias, out);
}